// round 16
// baseline (speedup 1.0000x reference)
#include <cuda_runtime.h>
#include <cuda_fp16.h>
#include <cstdint>

// Problem constants (fixed by reference setup_inputs)
#define C_CLS 256
#define S_SUP 5
#define Q_QRY 64
#define DIN   1024
#define ZD    128
#define CS    (C_CLS*S_SUP)              // 1280
#define CQ    (C_CLS*Q_QRY)              // 16384
#define M_TOT (CS+CQ)                    // 17664
#define NPAIRS (C_CLS*(Q_QRY*(Q_QRY-1)/2)) // 516096
#define EPSF  1e-8f
#define NSTG  64                          // k_gemm: K stages of 16
#define DLSTG 8                           // k_dloo: K stages of 16
#define RPAD  24                          // padded row length (halves) = 48B

// k_gemm smem halves/slot: Ah 3072 | Al 3072 | Bh 3072 | Bl 3072
#define G_BUF 12288                       // 24 KB / slot, 4 slots
// k_dloo smem halves/slot: Ah 3072 | Al 3072 | Bh 6144 | Bl 6144
#define D_BUF 18432                       // 36 KB / slot, 3 slots

// ---------------- device scratch (no allocations allowed) ----------------
__device__ __align__(16) float g_z[(size_t)M_TOT * ZD];        // ~9 MB
__device__ __align__(16) float g_proto2[C_CLS];                // ||proto_c||^2
__device__ __align__(16) float g_row2[M_TOT];                  // ||z_row||^2
// 32*W fp16 hi/lo images, natural padded: [k16(64)][n(128)][RPAD]
__device__ __align__(16) __half g_Wh[64 * 128 * RPAD];         // 384 KB
__device__ __align__(16) __half g_Wl[64 * 128 * RPAD];         // 384 KB
// protoT fp16 hi/lo images: [k16(8)][n(256)][RPAD]
__device__ __align__(16) __half g_Ph[8 * 256 * RPAD];          // 96 KB
__device__ __align__(16) __half g_Pl[8 * 256 * RPAD];          // 96 KB
__device__ float g_cos_sum;
__device__ float g_acc_cnt;

// ---------------- helpers ----------------
__device__ __forceinline__ uint32_t smem_u32(const void* p){
    uint32_t a; asm("{ .reg .u64 t; cvta.to.shared.u64 t, %1; cvt.u32.u64 %0, t; }"
                    : "=r"(a) : "l"(p));
    return a;
}
__device__ __forceinline__ void cp16(uint32_t saddr, const void* g){
    asm volatile("cp.async.cg.shared.global [%0], [%1], 16;" :: "r"(saddr), "l"(g));
}
#define CP_COMMIT() asm volatile("cp.async.commit_group;" ::: "memory")
#define CP_WAIT(n)  asm volatile("cp.async.wait_group %0;" :: "n"(n) : "memory")

// ldmatrix x4 (4 x m8n8 b16 matrices)
__device__ __forceinline__ void ldm4(uint32_t* r, uint32_t addr){
    asm volatile("ldmatrix.sync.aligned.m8n8.x4.shared.b16 {%0,%1,%2,%3}, [%4];"
        : "=r"(r[0]), "=r"(r[1]), "=r"(r[2]), "=r"(r[3]) : "r"(addr));
}
// D += A(16x16,row) * B(16x8,col)  fp16 inputs, fp32 accumulate
__device__ __forceinline__ void mma16(float4 &d, uint32_t a0, uint32_t a1,
                                      uint32_t a2, uint32_t a3,
                                      uint32_t b0, uint32_t b1){
    asm volatile("mma.sync.aligned.m16n8k16.row.col.f32.f16.f16.f32 "
        "{%0,%1,%2,%3}, {%4,%5,%6,%7}, {%8,%9}, {%0,%1,%2,%3};"
        : "+f"(d.x), "+f"(d.y), "+f"(d.z), "+f"(d.w)
        : "r"(a0), "r"(a1), "r"(a2), "r"(a3), "r"(b0), "r"(b1));
}
// split float4 (4 consecutive k) -> packed hi uint2 + lo uint2
__device__ __forceinline__ void hsplit4(float4 v, uint2 &hi, uint2 &lo){
    __half2 ha = __float22half2_rn(make_float2(v.x, v.y));
    __half2 hb = __float22half2_rn(make_float2(v.z, v.w));
    float2 fa = __half22float2(ha), fb = __half22float2(hb);
    __half2 la = __float22half2_rn(make_float2(v.x - fa.x, v.y - fa.y));
    __half2 lb = __float22half2_rn(make_float2(v.z - fb.x, v.w - fb.y));
    hi = make_uint2(*(uint32_t*)&ha, *(uint32_t*)&hb);
    lo = make_uint2(*(uint32_t*)&la, *(uint32_t*)&lb);
}

// =====================================================================
// KW: split 32*W into fp16 hi/lo NATURAL padded images [s][n][RPAD].
// =====================================================================
__global__ __launch_bounds__(256) void k_wsplit(const float* __restrict__ W){
    const int s = blockIdx.x;            // 0..63
    const int n = threadIdx.x >> 1;
    const int h = threadIdx.x & 1;
    const int kb = s * 16 + 8 * h;
    float4 v0, v1;
    v0.x = 32.f * W[(size_t)(kb + 0) * ZD + n];
    v0.y = 32.f * W[(size_t)(kb + 1) * ZD + n];
    v0.z = 32.f * W[(size_t)(kb + 2) * ZD + n];
    v0.w = 32.f * W[(size_t)(kb + 3) * ZD + n];
    v1.x = 32.f * W[(size_t)(kb + 4) * ZD + n];
    v1.y = 32.f * W[(size_t)(kb + 5) * ZD + n];
    v1.z = 32.f * W[(size_t)(kb + 6) * ZD + n];
    v1.w = 32.f * W[(size_t)(kb + 7) * ZD + n];
    uint2 h0, l0, h1, l1;
    hsplit4(v0, h0, l0);
    hsplit4(v1, h1, l1);
    const int off = s * (128 * RPAD) + n * RPAD + 8 * h;
    *(uint4*)&g_Wh[off] = make_uint4(h0.x, h0.y, h1.x, h1.y);
    *(uint4*)&g_Wl[off] = make_uint4(l0.x, l0.y, l1.x, l1.y);
}

// =====================================================================
// K1: z = [xs; xq] @ W, fp16 double-double (3-pass m16n8k16), ldmatrix
// fragments, 4-DEEP cp.async ring (B committed 3 stages ahead, A LDG
// 4 ahead / STS 2 ahead). 512 threads = 16 warps (4m x 4n), tile 32x32.
// Epilogue: z = acc/32 + fused ||row||^2.
// =====================================================================
__global__ __launch_bounds__(512) void k_gemm(const float* __restrict__ xs,
                                              const float* __restrict__ xq){
    extern __shared__ __half sh[];       // 4 x G_BUF halves (96 KB)
    __shared__ float s_r2[128];

    const int tid  = threadIdx.x;
    const int lane = tid & 31;
    const int wid  = tid >> 5;
    const int g    = lane >> 2;
    const int tg   = lane & 3;
    const int m0   = (wid & 3) * 32;
    const int n0   = (wid >> 2) * 32;
    const int bm   = blockIdx.x;
    const float* X = (bm < 10) ? (xs + (size_t)bm * (128 * DIN))
                               : (xq + (size_t)(bm - 10) * (128 * DIN));
    const int sm_m = tid >> 2;           // staging row 0..127
    const int sq   = tid & 3;            // k quad
    const uint32_t sbase = smem_u32(sh);

    // fragment addresses (bytes rel. to slot base)
    const int arow  = lane & 15;
    const int akoff = ((lane >> 4) & 1) * 8;
    uint32_t aAddr[2];
#pragma unroll
    for (int mt = 0; mt < 2; mt++)
        aAddr[mt] = sbase + ((m0 + mt * 16 + arow) * RPAD + akoff) * 2;
    const int brow  = (lane & 7) + ((lane >> 4) & 1) * 8;
    const int bkoff = ((lane >> 3) & 1) * 8;
    uint32_t bAddr[2];
#pragma unroll
    for (int jp = 0; jp < 2; jp++)
        bAddr[jp] = sbase + (6144 + (n0 + jp * 16 + brow) * RPAD + bkoff) * 2;

    float4 acc[2][4];
#pragma unroll
    for (int i = 0; i < 2; i++)
#pragma unroll
        for (int j = 0; j < 4; j++) acc[i][j] = make_float4(0.f, 0.f, 0.f, 0.f);

    // helpers
    auto issueB = [&](int t){
        const uint32_t nb = sbase + (uint32_t)(t & 3) * (G_BUF * 2);
        if (tid < 384)  cp16(nb + 12288 + tid * 16, g_Wh + t * (128 * RPAD) + tid * 8);
        if (tid >= 128) cp16(nb + 18432 + (tid - 128) * 16,
                             g_Wl + t * (128 * RPAD) + (tid - 128) * 8);
    };
    auto stsA = [&](int t, float4 raw){
        __half* buf = sh + (t & 3) * G_BUF;
        uint2 hi, lo;
        hsplit4(raw, hi, lo);
        *(uint2*)&buf[sm_m * RPAD + sq * 4]        = hi;
        *(uint2*)&buf[3072 + sm_m * RPAD + sq * 4] = lo;
    };

    float4 rring[2];
    // prologue: B slots 0..2 (3 groups), A stages 0..1 stored, raws 2,3
    issueB(0); CP_COMMIT();
    issueB(1); CP_COMMIT();
    issueB(2); CP_COMMIT();
#pragma unroll
    for (int t = 0; t < 2; t++)
        stsA(t, *(const float4*)(X + (size_t)sm_m * DIN + t * 16 + sq * 4));
    rring[0] = *(const float4*)(X + (size_t)sm_m * DIN + 2 * 16 + sq * 4);
    rring[1] = *(const float4*)(X + (size_t)sm_m * DIN + 3 * 16 + sq * 4);

    for (int s = 0; s < NSTG; s++){
        __syncthreads();                 // A s visible; slot s+3 (= s-1) free
        if (s + 3 < NSTG) issueB(s + 3);
        CP_COMMIT();                     // unconditional: keeps group count exact
        if (s + 2 < NSTG) stsA(s + 2, rring[s & 1]);
        if (s + 4 < NSTG)
            rring[s & 1] = *(const float4*)(X + (size_t)sm_m * DIN + (s + 4) * 16 + sq * 4);
        CP_WAIT(3);                      // B slot s complete

        const uint32_t boff = (uint32_t)(s & 3) * (G_BUF * 2);
        uint32_t ah[2][4], al[2][4];
#pragma unroll
        for (int mt = 0; mt < 2; mt++){
            ldm4(ah[mt], aAddr[mt] + boff);
            ldm4(al[mt], aAddr[mt] + boff + 6144);
        }
#pragma unroll
        for (int jp = 0; jp < 2; jp++){
            uint32_t bh[4], bl[4];
            ldm4(bh, bAddr[jp] + boff);
            ldm4(bl, bAddr[jp] + boff + 6144);
#pragma unroll
            for (int mt = 0; mt < 2; mt++){
                mma16(acc[mt][2*jp],   ah[mt][0], ah[mt][1], ah[mt][2], ah[mt][3], bh[0], bh[1]);
                mma16(acc[mt][2*jp+1], ah[mt][0], ah[mt][1], ah[mt][2], ah[mt][3], bh[2], bh[3]);
                mma16(acc[mt][2*jp],   al[mt][0], al[mt][1], al[mt][2], al[mt][3], bh[0], bh[1]);
                mma16(acc[mt][2*jp+1], al[mt][0], al[mt][1], al[mt][2], al[mt][3], bh[2], bh[3]);
                mma16(acc[mt][2*jp],   ah[mt][0], ah[mt][1], ah[mt][2], ah[mt][3], bl[0], bl[1]);
                mma16(acc[mt][2*jp+1], ah[mt][0], ah[mt][1], ah[mt][2], ah[mt][3], bl[2], bl[3]);
            }
        }
    }

    // ---- epilogue: z = acc/32, store + fused row norms ----
    __syncthreads();
    if (tid < 128) s_r2[tid] = 0.0f;
    __syncthreads();
    const size_t rb = (size_t)bm * 128;
    const float inv32 = 1.0f / 32.0f;
#pragma unroll
    for (int mt = 0; mt < 2; mt++){
        const int r0 = m0 + mt * 16 + g;
        float s0 = 0.0f, s1 = 0.0f;
#pragma unroll
        for (int j = 0; j < 4; j++){
            float4 a = acc[mt][j];
            a.x *= inv32; a.y *= inv32; a.z *= inv32; a.w *= inv32;
            const int col = n0 + j * 8 + 2 * tg;
            *(float2*)(g_z + (rb + r0) * ZD + col)     = make_float2(a.x, a.y);
            *(float2*)(g_z + (rb + r0 + 8) * ZD + col) = make_float2(a.z, a.w);
            s0 = fmaf(a.x, a.x, s0); s0 = fmaf(a.y, a.y, s0);
            s1 = fmaf(a.z, a.z, s1); s1 = fmaf(a.w, a.w, s1);
        }
        s0 += __shfl_xor_sync(0xffffffffu, s0, 1);
        s0 += __shfl_xor_sync(0xffffffffu, s0, 2);
        s1 += __shfl_xor_sync(0xffffffffu, s1, 1);
        s1 += __shfl_xor_sync(0xffffffffu, s1, 2);
        if (tg == 0){
            atomicAdd(&s_r2[r0],     s0);
            atomicAdd(&s_r2[r0 + 8], s1);
        }
    }
    __syncthreads();
    if (tid < 128) g_row2[rb + tid] = s_r2[tid];
}

// ---------------- K2: prototypes + ||proto||^2 + padded hi/lo images ----
__global__ __launch_bounds__(128) void k_proto(){
    const int c = blockIdx.x;
    const int d = threadIdx.x;  // 0..127 (= k index)
    if (c == 0 && d == 0){ g_cos_sum = 0.0f; g_acc_cnt = 0.0f; }
    const float* z = g_z + (size_t)c * S_SUP * ZD + d;
    float p = 0.0f;
#pragma unroll
    for (int s = 0; s < S_SUP; s++) p += z[s * ZD];
    p *= (1.0f / S_SUP);
    const __half hi = __float2half_rn(p);
    const int off = (d >> 4) * (256 * RPAD) + c * RPAD + (d & 15);
    g_Ph[off] = hi;
    g_Pl[off] = __float2half_rn(p - __half2float(hi));
    float sq = p * p;
#pragma unroll
    for (int o = 16; o; o >>= 1) sq += __shfl_xor_sync(0xffffffffu, sq, o);
    __shared__ float w[4];
    if ((d & 31) == 0) w[d >> 5] = sq;
    __syncthreads();
    if (d == 0) g_proto2[c] = w[0] + w[1] + w[2] + w[3];
}

// =====================================================================
// K3 (fused d2 + loo): one CTA per 2 classes. GEMM M=128 x N=256 x K=128,
// fp16 double-double 3-pass via ldmatrix.x4, 3-DEEP cp.async ring.
// 16 warps: 4m x 4n, warp tile 32x64. d2 -> SMEM then loo + cos + argmin.
// cos: sum_{q<k} a_q.a_k = ( ||sum_q a_q||^2 - sum_q ||a_q||^2 ) / 2
// =====================================================================
__global__ __launch_bounds__(512) void k_dloo(){
    extern __shared__ __half sh[];       // 3 slots + d2s alias
    __shared__ float s_part[16][256];
    __shared__ float s_red[16];
    __shared__ float s_scal[4];          // [sumA2_c0, cnt_c0, sumA2_c1, cnt_c1]

    const int tid  = threadIdx.x;
    const int lane = tid & 31;
    const int wid  = tid >> 5;           // 0..15
    const int g    = lane >> 2;
    const int tg   = lane & 3;
    const int m0   = (wid & 3) * 32;
    const int n0   = (wid >> 2) * 64;
    const int qb   = blockIdx.x;         // class pair
    const float* X = g_z + (size_t)(CS + qb * 128) * ZD;
    const int sm_m = tid >> 2;
    const int sq   = tid & 3;
    const uint32_t sbase = smem_u32(sh);

    if (tid < 4) s_scal[tid] = 0.0f;

    const int arow  = lane & 15;
    const int akoff = ((lane >> 4) & 1) * 8;
    uint32_t aAddr[2];
#pragma unroll
    for (int mt = 0; mt < 2; mt++)
        aAddr[mt] = sbase + ((m0 + mt * 16 + arow) * RPAD + akoff) * 2;
    const int brow  = (lane & 7) + ((lane >> 4) & 1) * 8;
    const int bkoff = ((lane >> 3) & 1) * 8;
    uint32_t bAddr[4];
#pragma unroll
    for (int jp = 0; jp < 4; jp++)
        bAddr[jp] = sbase + (6144 + (n0 + jp * 16 + brow) * RPAD + bkoff) * 2;

    float4 acc[2][8];
#pragma unroll
    for (int i = 0; i < 2; i++)
#pragma unroll
        for (int j = 0; j < 8; j++) acc[i][j] = make_float4(0.f, 0.f, 0.f, 0.f);

    auto issueB = [&](int t){
        const uint32_t nb = sbase + (uint32_t)(t % 3) * (D_BUF * 2);
        const __half* srcH = g_Ph + t * (256 * RPAD);
        const __half* srcL = g_Pl + t * (256 * RPAD);
#pragma unroll
        for (int e = 0; e < 2; e++){
            const int idx = tid + e * 512;
            if (idx < 768){
                cp16(nb + 12288 + idx * 16, srcH + idx * 8);
                cp16(nb + 24576 + idx * 16, srcL + idx * 8);
            }
        }
    };
    auto stsA = [&](int t, float4 raw){
        __half* buf = sh + (t % 3) * D_BUF;
        uint2 hi, lo;
        hsplit4(raw, hi, lo);
        *(uint2*)&buf[sm_m * RPAD + sq * 4]        = hi;
        *(uint2*)&buf[3072 + sm_m * RPAD + sq * 4] = lo;
    };

    float4 rring[2];
    // prologue: B slots 0,1 (2 groups), A stages 0,1, raws 2,3
    issueB(0); CP_COMMIT();
    issueB(1); CP_COMMIT();
#pragma unroll
    for (int t = 0; t < 2; t++)
        stsA(t, *(const float4*)(X + (size_t)sm_m * ZD + t * 16 + sq * 4));
    rring[0] = *(const float4*)(X + (size_t)sm_m * ZD + 2 * 16 + sq * 4);
    rring[1] = *(const float4*)(X + (size_t)sm_m * ZD + 3 * 16 + sq * 4);

    for (int s = 0; s < DLSTG; s++){
        __syncthreads();
        if (s + 2 < DLSTG) issueB(s + 2);
        CP_COMMIT();
        if (s + 2 < DLSTG) stsA(s + 2, rring[s & 1]);
        if (s + 4 < DLSTG)
            rring[s & 1] = *(const float4*)(X + (size_t)sm_m * ZD + (s + 4) * 16 + sq * 4);
        CP_WAIT(2);

        const uint32_t boff = (uint32_t)(s % 3) * (D_BUF * 2);
        uint32_t ah[2][4], al[2][4];
#pragma unroll
        for (int mt = 0; mt < 2; mt++){
            ldm4(ah[mt], aAddr[mt] + boff);
            ldm4(al[mt], aAddr[mt] + boff + 6144);
        }
#pragma unroll
        for (int jp = 0; jp < 4; jp++){
            uint32_t bh[4], bl[4];
            ldm4(bh, bAddr[jp] + boff);
            ldm4(bl, bAddr[jp] + boff + 12288);
#pragma unroll
            for (int mt = 0; mt < 2; mt++){
                mma16(acc[mt][2*jp],   ah[mt][0], ah[mt][1], ah[mt][2], ah[mt][3], bh[0], bh[1]);
                mma16(acc[mt][2*jp+1], ah[mt][0], ah[mt][1], ah[mt][2], ah[mt][3], bh[2], bh[3]);
                mma16(acc[mt][2*jp],   al[mt][0], al[mt][1], al[mt][2], al[mt][3], bh[0], bh[1]);
                mma16(acc[mt][2*jp+1], al[mt][0], al[mt][1], al[mt][2], al[mt][3], bh[2], bh[3]);
                mma16(acc[mt][2*jp],   ah[mt][0], ah[mt][1], ah[mt][2], ah[mt][3], bl[0], bl[1]);
                mma16(acc[mt][2*jp+1], ah[mt][0], ah[mt][1], ah[mt][2], ah[mt][3], bl[2], bl[3]);
            }
        }
    }

    // ---- d2 into SMEM (reuses stage buffers; stride 264 floats) ----
    __syncthreads();                     // all warps done reading buffers
    float* d2s = (float*)sh;             // 128 x 264 floats
#pragma unroll
    for (int mt = 0; mt < 2; mt++){
        const int r = m0 + mt * 16 + g;
        const float qn0 = g_row2[CS + qb * 128 + r];
        const float qn1 = g_row2[CS + qb * 128 + r + 8];
#pragma unroll
        for (int j = 0; j < 8; j++){
            const int col = n0 + j * 8 + 2 * tg;
            const float pn0 = g_proto2[col];
            const float pn1 = g_proto2[col + 1];
            const float4 a = acc[mt][j];
            *(float2*)&d2s[r * 264 + col] =
                make_float2(qn0 + pn0 - 2.0f * a.x, qn0 + pn1 - 2.0f * a.y);
            *(float2*)&d2s[(r + 8) * 264 + col] =
                make_float2(qn1 + pn0 - 2.0f * a.z, qn1 + pn1 - 2.0f * a.w);
        }
    }
    __syncthreads();

    // ---- loo: warp w -> rows w*8..w*8+7; class = 2qb + (w>>3) ----
    const int cls = 2 * qb + (wid >> 3);
    const float* D = d2s + (size_t)(wid * 8) * 264 + lane * 8;
    float d2v[8][8];
#pragma unroll
    for (int r = 0; r < 8; r++){
        const float4 v0 = *(const float4*)(D + r * 264);
        const float4 v1 = *(const float4*)(D + r * 264 + 4);
        d2v[r][0] = v0.x; d2v[r][1] = v0.y; d2v[r][2] = v0.z; d2v[r][3] = v0.w;
        d2v[r][4] = v1.x; d2v[r][5] = v1.y; d2v[r][6] = v1.z; d2v[r][7] = v1.w;
    }

    float sacc[8];
#pragma unroll
    for (int j = 0; j < 8; j++) sacc[j] = 0.0f;
    float sumA2 = 0.0f;
    float cnt   = 0.0f;

#pragma unroll
    for (int r = 0; r < 8; r++){
        float ss = 0.0f;
        float mv = 3.4e38f;
        int   mi = 1 << 30;
#pragma unroll
        for (int j = 0; j < 8; j++){
            const int   p = lane * 8 + j;
            const float v = d2v[r][j];
            if (v < mv){ mv = v; mi = p; }        // ascending -> first min
            if (p != cls) ss = fmaf(v, v, ss);
        }
#pragma unroll
        for (int off = 16; off; off >>= 1){
            ss += __shfl_xor_sync(0xffffffffu, ss, off);
            const float ov = __shfl_xor_sync(0xffffffffu, mv, off);
            const int   oi = __shfl_xor_sync(0xffffffffu, mi, off);
            if (ov < mv || (ov == mv && oi < mi)){ mv = ov; mi = oi; }
        }
        const float inv = 1.0f / fmaxf(sqrtf(ss), EPSF);
#pragma unroll
        for (int j = 0; j < 8; j++){
            const int p = lane * 8 + j;
            if (p != cls) sacc[j] = fmaf(d2v[r][j], inv, sacc[j]);
        }
        if (lane == 0){
            sumA2 += ss * inv * inv;
            if (mi == cls) cnt += 1.0f;
        }
    }

#pragma unroll
    for (int j = 0; j < 8; j++) s_part[wid][lane * 8 + j] = sacc[j];
    if (lane == 0){
        atomicAdd(&s_scal[(wid >> 3) * 2],     sumA2);
        atomicAdd(&s_scal[(wid >> 3) * 2 + 1], cnt);
    }
    __syncthreads();

    // ||sum_q a_q||^2 per class: threads 0-255 -> class0, 256-511 -> class1
    {
        const int half = tid >> 8;
        const int cc   = tid & 255;
        float col = 0.0f;
#pragma unroll
        for (int w2 = 0; w2 < 8; w2++) col += s_part[half * 8 + w2][cc];
        float sq = col * col;
#pragma unroll
        for (int off = 16; off; off >>= 1) sq += __shfl_xor_sync(0xffffffffu, sq, off);
        if (lane == 0) s_red[wid] = sq;
    }
    __syncthreads();
    if (tid == 0){
        float S20 = 0.0f, S21 = 0.0f;
#pragma unroll
        for (int i = 0; i < 8; i++){ S20 += s_red[i]; S21 += s_red[8 + i]; }
        atomicAdd(&g_cos_sum, 0.5f * ((S20 - s_scal[0]) + (S21 - s_scal[2])));
        atomicAdd(&g_acc_cnt, s_scal[1] + s_scal[3]);
    }
}

// ---------------- K4: finalize -------------------------------------------
__global__ void k_final(float* __restrict__ out){
    if (threadIdx.x == 0){
        out[0] = g_cos_sum / (float)NPAIRS;
        out[1] = g_acc_cnt / (float)CQ;
    }
}

// ---------------- launch ---------------------------------------------------
extern "C" void kernel_launch(void* const* d_in, const int* in_sizes, int n_in,
                              void* d_out, int out_size){
    const float* xs = (const float*)d_in[0];
    const float* xq = (const float*)d_in[1];
    const float* W  = (const float*)d_in[2];
    float* out = (float*)d_out;
    (void)in_sizes; (void)n_in; (void)out_size;

    const int smem_gemm = 4 * G_BUF * (int)sizeof(__half);      // 96 KB
    int smem_dloo = 3 * D_BUF * (int)sizeof(__half);            // 110.6 KB
    const int smem_d2s = 128 * 264 * (int)sizeof(float);        // 135.2 KB
    if (smem_d2s > smem_dloo) smem_dloo = smem_d2s;
    cudaFuncSetAttribute(k_gemm, cudaFuncAttributeMaxDynamicSharedMemorySize, smem_gemm);
    cudaFuncSetAttribute(k_dloo, cudaFuncAttributeMaxDynamicSharedMemorySize, smem_dloo);

    k_wsplit<<<64, 256>>>(W);
    k_gemm<<<M_TOT / 128, 512, smem_gemm>>>(xs, xq);
    k_proto<<<C_CLS, 128>>>();
    k_dloo<<<128, 512, smem_dloo>>>();
    k_final<<<1, 1>>>(out);
}

// round 17
// speedup vs baseline: 1.1206x; 1.1206x over previous
#include <cuda_runtime.h>
#include <cuda_fp16.h>
#include <cstdint>

// Problem constants (fixed by reference setup_inputs)
#define C_CLS 256
#define S_SUP 5
#define Q_QRY 64
#define DIN   1024
#define ZD    128
#define CS    (C_CLS*S_SUP)              // 1280
#define CQ    (C_CLS*Q_QRY)              // 16384
#define M_TOT (CS+CQ)                    // 17664
#define NPAIRS (C_CLS*(Q_QRY*(Q_QRY-1)/2)) // 516096
#define EPSF  1e-8f
#define NSTG  64                          // k_gemm: K stages of 16
#define DLSTG 8                           // k_dloo: K stages of 16
#define RPAD  24                          // padded row length (halves) = 48B

// k_gemm smem halves/buffer: Ah 3072 | Al 3072 | Bh 3072 | Bl 3072
#define G_BUF 12288                       // 24 KB / buffer, 2 buffers
// k_dloo smem halves/slot: Ah 3072 | Al 3072 | Bh 6144 | Bl 6144
#define D_BUF 18432                       // 36 KB / slot, 3 slots

// ---------------- device scratch (no allocations allowed) ----------------
__device__ __align__(16) float g_z[(size_t)M_TOT * ZD];        // ~9 MB
__device__ __align__(16) float g_proto2[C_CLS];                // ||proto_c||^2
__device__ __align__(16) float g_row2[M_TOT];                  // ||z_row||^2
// 32*W fp16 hi/lo images, natural padded: [k16(64)][n(128)][RPAD]
__device__ __align__(16) __half g_Wh[64 * 128 * RPAD];         // 384 KB
__device__ __align__(16) __half g_Wl[64 * 128 * RPAD];         // 384 KB
// protoT fp16 hi/lo images: [k16(8)][n(256)][RPAD]
__device__ __align__(16) __half g_Ph[8 * 256 * RPAD];          // 96 KB
__device__ __align__(16) __half g_Pl[8 * 256 * RPAD];          // 96 KB
__device__ float g_cos_sum;
__device__ float g_acc_cnt;

// ---------------- helpers ----------------
__device__ __forceinline__ uint32_t smem_u32(const void* p){
    uint32_t a; asm("{ .reg .u64 t; cvta.to.shared.u64 t, %1; cvt.u32.u64 %0, t; }"
                    : "=r"(a) : "l"(p));
    return a;
}
__device__ __forceinline__ void cp16(uint32_t saddr, const void* g){
    asm volatile("cp.async.cg.shared.global [%0], [%1], 16;" :: "r"(saddr), "l"(g));
}
#define CP_COMMIT() asm volatile("cp.async.commit_group;" ::: "memory")
#define CP_WAIT(n)  asm volatile("cp.async.wait_group %0;" :: "n"(n) : "memory")

// ldmatrix x4 (4 x m8n8 b16 matrices)
__device__ __forceinline__ void ldm4(uint32_t* r, uint32_t addr){
    asm volatile("ldmatrix.sync.aligned.m8n8.x4.shared.b16 {%0,%1,%2,%3}, [%4];"
        : "=r"(r[0]), "=r"(r[1]), "=r"(r[2]), "=r"(r[3]) : "r"(addr));
}
// D += A(16x16,row) * B(16x8,col)  fp16 inputs, fp32 accumulate
__device__ __forceinline__ void mma16(float4 &d, uint32_t a0, uint32_t a1,
                                      uint32_t a2, uint32_t a3,
                                      uint32_t b0, uint32_t b1){
    asm volatile("mma.sync.aligned.m16n8k16.row.col.f32.f16.f16.f32 "
        "{%0,%1,%2,%3}, {%4,%5,%6,%7}, {%8,%9}, {%0,%1,%2,%3};"
        : "+f"(d.x), "+f"(d.y), "+f"(d.z), "+f"(d.w)
        : "r"(a0), "r"(a1), "r"(a2), "r"(a3), "r"(b0), "r"(b1));
}
// split float4 (4 consecutive k) -> packed hi uint2 + lo uint2
__device__ __forceinline__ void hsplit4(float4 v, uint2 &hi, uint2 &lo){
    __half2 ha = __float22half2_rn(make_float2(v.x, v.y));
    __half2 hb = __float22half2_rn(make_float2(v.z, v.w));
    float2 fa = __half22float2(ha), fb = __half22float2(hb);
    __half2 la = __float22half2_rn(make_float2(v.x - fa.x, v.y - fa.y));
    __half2 lb = __float22half2_rn(make_float2(v.z - fb.x, v.w - fb.y));
    hi = make_uint2(*(uint32_t*)&ha, *(uint32_t*)&hb);
    lo = make_uint2(*(uint32_t*)&la, *(uint32_t*)&lb);
}

// =====================================================================
// KW: split 32*W into fp16 hi/lo NATURAL padded images [s][n][RPAD].
// =====================================================================
__global__ __launch_bounds__(256) void k_wsplit(const float* __restrict__ W){
    const int s = blockIdx.x;            // 0..63
    const int n = threadIdx.x >> 1;
    const int h = threadIdx.x & 1;
    const int kb = s * 16 + 8 * h;
    float4 v0, v1;
    v0.x = 32.f * W[(size_t)(kb + 0) * ZD + n];
    v0.y = 32.f * W[(size_t)(kb + 1) * ZD + n];
    v0.z = 32.f * W[(size_t)(kb + 2) * ZD + n];
    v0.w = 32.f * W[(size_t)(kb + 3) * ZD + n];
    v1.x = 32.f * W[(size_t)(kb + 4) * ZD + n];
    v1.y = 32.f * W[(size_t)(kb + 5) * ZD + n];
    v1.z = 32.f * W[(size_t)(kb + 6) * ZD + n];
    v1.w = 32.f * W[(size_t)(kb + 7) * ZD + n];
    uint2 h0, l0, h1, l1;
    hsplit4(v0, h0, l0);
    hsplit4(v1, h1, l1);
    const int off = s * (128 * RPAD) + n * RPAD + 8 * h;
    *(uint4*)&g_Wh[off] = make_uint4(h0.x, h0.y, h1.x, h1.y);
    *(uint4*)&g_Wl[off] = make_uint4(l0.x, l0.y, l1.x, l1.y);
}

// =====================================================================
// K1 (R15 version, measured ~46us): z = [xs; xq] @ W, fp16 double-double
// (3-pass m16n8k16), ldmatrix.x4 fragments, double-buffered (2x24KB).
// 512 threads = 16 warps (4m x 4n), warp tile 32x32, 64 stages.
// Epilogue: z = acc/32 + fused ||row||^2.
// =====================================================================
__global__ __launch_bounds__(512) void k_gemm(const float* __restrict__ xs,
                                              const float* __restrict__ xq){
    extern __shared__ __half sh[];       // 2 x G_BUF halves (48 KB)
    __shared__ float s_r2[128];

    const int tid  = threadIdx.x;
    const int lane = tid & 31;
    const int wid  = tid >> 5;
    const int g    = lane >> 2;
    const int tg   = lane & 3;
    const int m0   = (wid & 3) * 32;
    const int n0   = (wid >> 2) * 32;
    const int bm   = blockIdx.x;
    const float* X = (bm < 10) ? (xs + (size_t)bm * (128 * DIN))
                               : (xq + (size_t)(bm - 10) * (128 * DIN));
    const int sm_m = tid >> 2;           // staging row 0..127
    const int sq   = tid & 3;            // k quad
    const uint32_t sbase = smem_u32(sh);

    // fragment addresses (bytes rel. to buffer): A mats T00,T10,T01,T11
    const int arow  = lane & 15;
    const int akoff = ((lane >> 4) & 1) * 8;
    uint32_t aAddr[2];
#pragma unroll
    for (int mt = 0; mt < 2; mt++)
        aAddr[mt] = sbase + ((m0 + mt * 16 + arow) * RPAD + akoff) * 2;
    const int brow  = (lane & 7) + ((lane >> 4) & 1) * 8;
    const int bkoff = ((lane >> 3) & 1) * 8;
    uint32_t bAddr[2];
#pragma unroll
    for (int jp = 0; jp < 2; jp++)
        bAddr[jp] = sbase + (6144 + (n0 + jp * 16 + brow) * RPAD + bkoff) * 2;

    float4 acc[2][4];
#pragma unroll
    for (int i = 0; i < 2; i++)
#pragma unroll
        for (int j = 0; j < 4; j++) acc[i][j] = make_float4(0.f, 0.f, 0.f, 0.f);

    float4 rA;
    // prologue: stage 0
    {
        if (tid < 384)  cp16(sbase + 12288 + tid * 16, g_Wh + tid * 8);
        if (tid >= 128) cp16(sbase + 18432 + (tid - 128) * 16, g_Wl + (tid - 128) * 8);
        CP_COMMIT();
        rA = *(const float4*)(X + (size_t)sm_m * DIN + sq * 4);
        uint2 hi, lo;
        hsplit4(rA, hi, lo);
        *(uint2*)&sh[sm_m * RPAD + sq * 4]        = hi;
        *(uint2*)&sh[3072 + sm_m * RPAD + sq * 4] = lo;
        CP_WAIT(0);
    }
    __syncthreads();

    for (int s = 0; s < NSTG; s++){
        const int b = s & 1;
        const uint32_t boff = b * (G_BUF * 2);
        __half* nbuf = sh + (b ^ 1) * G_BUF;
        if (s + 1 < NSTG){
            const uint32_t nb = sbase + (b ^ 1) * (G_BUF * 2);
            const __half* srcH = g_Wh + (s + 1) * (128 * RPAD);
            const __half* srcL = g_Wl + (s + 1) * (128 * RPAD);
            if (tid < 384)  cp16(nb + 12288 + tid * 16, srcH + tid * 8);
            if (tid >= 128) cp16(nb + 18432 + (tid - 128) * 16, srcL + (tid - 128) * 8);
            CP_COMMIT();
            rA = *(const float4*)(X + (size_t)sm_m * DIN + (s + 1) * 16 + sq * 4);
        }
        // A fragments: 4 ldmatrix.x4 (mt x hi/lo)
        uint32_t ah[2][4], al[2][4];
#pragma unroll
        for (int mt = 0; mt < 2; mt++){
            ldm4(ah[mt], aAddr[mt] + boff);
            ldm4(al[mt], aAddr[mt] + boff + 6144);
        }
#pragma unroll
        for (int jp = 0; jp < 2; jp++){
            uint32_t bh[4], bl[4];
            ldm4(bh, bAddr[jp] + boff);
            ldm4(bl, bAddr[jp] + boff + 6144);
#pragma unroll
            for (int mt = 0; mt < 2; mt++){
                mma16(acc[mt][2*jp],   ah[mt][0], ah[mt][1], ah[mt][2], ah[mt][3], bh[0], bh[1]);
                mma16(acc[mt][2*jp+1], ah[mt][0], ah[mt][1], ah[mt][2], ah[mt][3], bh[2], bh[3]);
                mma16(acc[mt][2*jp],   al[mt][0], al[mt][1], al[mt][2], al[mt][3], bh[0], bh[1]);
                mma16(acc[mt][2*jp+1], al[mt][0], al[mt][1], al[mt][2], al[mt][3], bh[2], bh[3]);
                mma16(acc[mt][2*jp],   ah[mt][0], ah[mt][1], ah[mt][2], ah[mt][3], bl[0], bl[1]);
                mma16(acc[mt][2*jp+1], ah[mt][0], ah[mt][1], ah[mt][2], ah[mt][3], bl[2], bl[3]);
            }
        }
        if (s + 1 < NSTG){
            uint2 hi, lo;
            hsplit4(rA, hi, lo);
            *(uint2*)&nbuf[sm_m * RPAD + sq * 4]        = hi;
            *(uint2*)&nbuf[3072 + sm_m * RPAD + sq * 4] = lo;
            CP_WAIT(0);
            __syncthreads();
        }
    }

    // ---- epilogue: z = acc/32, store + fused row norms ----
    if (tid < 128) s_r2[tid] = 0.0f;
    __syncthreads();
    const size_t rb = (size_t)bm * 128;
    const float inv32 = 1.0f / 32.0f;
#pragma unroll
    for (int mt = 0; mt < 2; mt++){
        const int r0 = m0 + mt * 16 + g;
        float s0 = 0.0f, s1 = 0.0f;
#pragma unroll
        for (int j = 0; j < 4; j++){
            float4 a = acc[mt][j];
            a.x *= inv32; a.y *= inv32; a.z *= inv32; a.w *= inv32;
            const int col = n0 + j * 8 + 2 * tg;
            *(float2*)(g_z + (rb + r0) * ZD + col)     = make_float2(a.x, a.y);
            *(float2*)(g_z + (rb + r0 + 8) * ZD + col) = make_float2(a.z, a.w);
            s0 = fmaf(a.x, a.x, s0); s0 = fmaf(a.y, a.y, s0);
            s1 = fmaf(a.z, a.z, s1); s1 = fmaf(a.w, a.w, s1);
        }
        s0 += __shfl_xor_sync(0xffffffffu, s0, 1);
        s0 += __shfl_xor_sync(0xffffffffu, s0, 2);
        s1 += __shfl_xor_sync(0xffffffffu, s1, 1);
        s1 += __shfl_xor_sync(0xffffffffu, s1, 2);
        if (tg == 0){
            atomicAdd(&s_r2[r0],     s0);
            atomicAdd(&s_r2[r0 + 8], s1);
        }
    }
    __syncthreads();
    if (tid < 128) g_row2[rb + tid] = s_r2[tid];
}

// ---------------- K2: prototypes + ||proto||^2 + padded hi/lo images ----
__global__ __launch_bounds__(128) void k_proto(){
    const int c = blockIdx.x;
    const int d = threadIdx.x;  // 0..127 (= k index)
    if (c == 0 && d == 0){ g_cos_sum = 0.0f; g_acc_cnt = 0.0f; }
    const float* z = g_z + (size_t)c * S_SUP * ZD + d;
    float p = 0.0f;
#pragma unroll
    for (int s = 0; s < S_SUP; s++) p += z[s * ZD];
    p *= (1.0f / S_SUP);
    const __half hi = __float2half_rn(p);
    const int off = (d >> 4) * (256 * RPAD) + c * RPAD + (d & 15);
    g_Ph[off] = hi;
    g_Pl[off] = __float2half_rn(p - __half2float(hi));
    float sq = p * p;
#pragma unroll
    for (int o = 16; o; o >>= 1) sq += __shfl_xor_sync(0xffffffffu, sq, o);
    __shared__ float w[4];
    if ((d & 31) == 0) w[d >> 5] = sq;
    __syncthreads();
    if (d == 0) g_proto2[c] = w[0] + w[1] + w[2] + w[3];
}

// =====================================================================
// K3 (R16 version, measured 21.5us): fused d2 + loo, one CTA per 2
// classes. GEMM M=128 x N=256 x K=128, fp16 double-double 3-pass via
// ldmatrix.x4, 3-DEEP cp.async ring. 16 warps: 4m x 4n, tile 32x64.
// d2 -> SMEM (stride 264) then loo-norm + cos identity + argmin.
// cos: sum_{q<k} a_q.a_k = ( ||sum_q a_q||^2 - sum_q ||a_q||^2 ) / 2
// =====================================================================
__global__ __launch_bounds__(512) void k_dloo(){
    extern __shared__ __half sh[];       // 3 slots + d2s alias
    __shared__ float s_part[16][256];
    __shared__ float s_red[16];
    __shared__ float s_scal[4];          // [sumA2_c0, cnt_c0, sumA2_c1, cnt_c1]

    const int tid  = threadIdx.x;
    const int lane = tid & 31;
    const int wid  = tid >> 5;           // 0..15
    const int g    = lane >> 2;
    const int tg   = lane & 3;
    const int m0   = (wid & 3) * 32;
    const int n0   = (wid >> 2) * 64;
    const int qb   = blockIdx.x;         // class pair
    const float* X = g_z + (size_t)(CS + qb * 128) * ZD;
    const int sm_m = tid >> 2;
    const int sq   = tid & 3;
    const uint32_t sbase = smem_u32(sh);

    if (tid < 4) s_scal[tid] = 0.0f;

    const int arow  = lane & 15;
    const int akoff = ((lane >> 4) & 1) * 8;
    uint32_t aAddr[2];
#pragma unroll
    for (int mt = 0; mt < 2; mt++)
        aAddr[mt] = sbase + ((m0 + mt * 16 + arow) * RPAD + akoff) * 2;
    const int brow  = (lane & 7) + ((lane >> 4) & 1) * 8;
    const int bkoff = ((lane >> 3) & 1) * 8;
    uint32_t bAddr[4];
#pragma unroll
    for (int jp = 0; jp < 4; jp++)
        bAddr[jp] = sbase + (6144 + (n0 + jp * 16 + brow) * RPAD + bkoff) * 2;

    float4 acc[2][8];
#pragma unroll
    for (int i = 0; i < 2; i++)
#pragma unroll
        for (int j = 0; j < 8; j++) acc[i][j] = make_float4(0.f, 0.f, 0.f, 0.f);

    auto issueB = [&](int t){
        const uint32_t nb = sbase + (uint32_t)(t % 3) * (D_BUF * 2);
        const __half* srcH = g_Ph + t * (256 * RPAD);
        const __half* srcL = g_Pl + t * (256 * RPAD);
#pragma unroll
        for (int e = 0; e < 2; e++){
            const int idx = tid + e * 512;
            if (idx < 768){
                cp16(nb + 12288 + idx * 16, srcH + idx * 8);
                cp16(nb + 24576 + idx * 16, srcL + idx * 8);
            }
        }
    };
    auto stsA = [&](int t, float4 raw){
        __half* buf = sh + (t % 3) * D_BUF;
        uint2 hi, lo;
        hsplit4(raw, hi, lo);
        *(uint2*)&buf[sm_m * RPAD + sq * 4]        = hi;
        *(uint2*)&buf[3072 + sm_m * RPAD + sq * 4] = lo;
    };

    float4 rring[2];
    // prologue: B slots 0,1 (2 groups), A stages 0,1, raws 2,3
    issueB(0); CP_COMMIT();
    issueB(1); CP_COMMIT();
#pragma unroll
    for (int t = 0; t < 2; t++)
        stsA(t, *(const float4*)(X + (size_t)sm_m * ZD + t * 16 + sq * 4));
    rring[0] = *(const float4*)(X + (size_t)sm_m * ZD + 2 * 16 + sq * 4);
    rring[1] = *(const float4*)(X + (size_t)sm_m * ZD + 3 * 16 + sq * 4);

    for (int s = 0; s < DLSTG; s++){
        __syncthreads();
        if (s + 2 < DLSTG) issueB(s + 2);
        CP_COMMIT();
        if (s + 2 < DLSTG) stsA(s + 2, rring[s & 1]);
        if (s + 4 < DLSTG)
            rring[s & 1] = *(const float4*)(X + (size_t)sm_m * ZD + (s + 4) * 16 + sq * 4);
        CP_WAIT(2);

        const uint32_t boff = (uint32_t)(s % 3) * (D_BUF * 2);
        uint32_t ah[2][4], al[2][4];
#pragma unroll
        for (int mt = 0; mt < 2; mt++){
            ldm4(ah[mt], aAddr[mt] + boff);
            ldm4(al[mt], aAddr[mt] + boff + 6144);
        }
#pragma unroll
        for (int jp = 0; jp < 4; jp++){
            uint32_t bh[4], bl[4];
            ldm4(bh, bAddr[jp] + boff);
            ldm4(bl, bAddr[jp] + boff + 12288);
#pragma unroll
            for (int mt = 0; mt < 2; mt++){
                mma16(acc[mt][2*jp],   ah[mt][0], ah[mt][1], ah[mt][2], ah[mt][3], bh[0], bh[1]);
                mma16(acc[mt][2*jp+1], ah[mt][0], ah[mt][1], ah[mt][2], ah[mt][3], bh[2], bh[3]);
                mma16(acc[mt][2*jp],   al[mt][0], al[mt][1], al[mt][2], al[mt][3], bh[0], bh[1]);
                mma16(acc[mt][2*jp+1], al[mt][0], al[mt][1], al[mt][2], al[mt][3], bh[2], bh[3]);
                mma16(acc[mt][2*jp],   ah[mt][0], ah[mt][1], ah[mt][2], ah[mt][3], bl[0], bl[1]);
                mma16(acc[mt][2*jp+1], ah[mt][0], ah[mt][1], ah[mt][2], ah[mt][3], bl[2], bl[3]);
            }
        }
    }

    // ---- d2 into SMEM (reuses stage buffers; stride 264 floats) ----
    __syncthreads();                     // all warps done reading buffers
    float* d2s = (float*)sh;             // 128 x 264 floats
#pragma unroll
    for (int mt = 0; mt < 2; mt++){
        const int r = m0 + mt * 16 + g;
        const float qn0 = g_row2[CS + qb * 128 + r];
        const float qn1 = g_row2[CS + qb * 128 + r + 8];
#pragma unroll
        for (int j = 0; j < 8; j++){
            const int col = n0 + j * 8 + 2 * tg;
            const float pn0 = g_proto2[col];
            const float pn1 = g_proto2[col + 1];
            const float4 a = acc[mt][j];
            *(float2*)&d2s[r * 264 + col] =
                make_float2(qn0 + pn0 - 2.0f * a.x, qn0 + pn1 - 2.0f * a.y);
            *(float2*)&d2s[(r + 8) * 264 + col] =
                make_float2(qn1 + pn0 - 2.0f * a.z, qn1 + pn1 - 2.0f * a.w);
        }
    }
    __syncthreads();

    // ---- loo: warp w -> rows w*8..w*8+7; class = 2qb + (w>>3) ----
    const int cls = 2 * qb + (wid >> 3);
    const float* D = d2s + (size_t)(wid * 8) * 264 + lane * 8;
    float d2v[8][8];
#pragma unroll
    for (int r = 0; r < 8; r++){
        const float4 v0 = *(const float4*)(D + r * 264);
        const float4 v1 = *(const float4*)(D + r * 264 + 4);
        d2v[r][0] = v0.x; d2v[r][1] = v0.y; d2v[r][2] = v0.z; d2v[r][3] = v0.w;
        d2v[r][4] = v1.x; d2v[r][5] = v1.y; d2v[r][6] = v1.z; d2v[r][7] = v1.w;
    }

    float sacc[8];
#pragma unroll
    for (int j = 0; j < 8; j++) sacc[j] = 0.0f;
    float sumA2 = 0.0f;
    float cnt   = 0.0f;

#pragma unroll
    for (int r = 0; r < 8; r++){
        float ss = 0.0f;
        float mv = 3.4e38f;
        int   mi = 1 << 30;
#pragma unroll
        for (int j = 0; j < 8; j++){
            const int   p = lane * 8 + j;
            const float v = d2v[r][j];
            if (v < mv){ mv = v; mi = p; }        // ascending -> first min
            if (p != cls) ss = fmaf(v, v, ss);
        }
#pragma unroll
        for (int off = 16; off; off >>= 1){
            ss += __shfl_xor_sync(0xffffffffu, ss, off);
            const float ov = __shfl_xor_sync(0xffffffffu, mv, off);
            const int   oi = __shfl_xor_sync(0xffffffffu, mi, off);
            if (ov < mv || (ov == mv && oi < mi)){ mv = ov; mi = oi; }
        }
        const float inv = 1.0f / fmaxf(sqrtf(ss), EPSF);
#pragma unroll
        for (int j = 0; j < 8; j++){
            const int p = lane * 8 + j;
            if (p != cls) sacc[j] = fmaf(d2v[r][j], inv, sacc[j]);
        }
        if (lane == 0){
            sumA2 += ss * inv * inv;
            if (mi == cls) cnt += 1.0f;
        }
    }

#pragma unroll
    for (int j = 0; j < 8; j++) s_part[wid][lane * 8 + j] = sacc[j];
    if (lane == 0){
        atomicAdd(&s_scal[(wid >> 3) * 2],     sumA2);
        atomicAdd(&s_scal[(wid >> 3) * 2 + 1], cnt);
    }
    __syncthreads();

    // ||sum_q a_q||^2 per class: threads 0-255 -> class0, 256-511 -> class1
    {
        const int half = tid >> 8;
        const int cc   = tid & 255;
        float col = 0.0f;
#pragma unroll
        for (int w2 = 0; w2 < 8; w2++) col += s_part[half * 8 + w2][cc];
        float sq = col * col;
#pragma unroll
        for (int off = 16; off; off >>= 1) sq += __shfl_xor_sync(0xffffffffu, sq, off);
        if (lane == 0) s_red[wid] = sq;
    }
    __syncthreads();
    if (tid == 0){
        float S20 = 0.0f, S21 = 0.0f;
#pragma unroll
        for (int i = 0; i < 8; i++){ S20 += s_red[i]; S21 += s_red[8 + i]; }
        atomicAdd(&g_cos_sum, 0.5f * ((S20 - s_scal[0]) + (S21 - s_scal[2])));
        atomicAdd(&g_acc_cnt, s_scal[1] + s_scal[3]);
    }
}

// ---------------- K4: finalize -------------------------------------------
__global__ void k_final(float* __restrict__ out){
    if (threadIdx.x == 0){
        out[0] = g_cos_sum / (float)NPAIRS;
        out[1] = g_acc_cnt / (float)CQ;
    }
}

// ---------------- launch ---------------------------------------------------
extern "C" void kernel_launch(void* const* d_in, const int* in_sizes, int n_in,
                              void* d_out, int out_size){
    const float* xs = (const float*)d_in[0];
    const float* xq = (const float*)d_in[1];
    const float* W  = (const float*)d_in[2];
    float* out = (float*)d_out;
    (void)in_sizes; (void)n_in; (void)out_size;

    const int smem_gemm = 2 * G_BUF * (int)sizeof(__half);      // 48 KB
    int smem_dloo = 3 * D_BUF * (int)sizeof(__half);            // 110.6 KB
    const int smem_d2s = 128 * 264 * (int)sizeof(float);        // 135.2 KB
    if (smem_d2s > smem_dloo) smem_dloo = smem_d2s;
    cudaFuncSetAttribute(k_gemm, cudaFuncAttributeMaxDynamicSharedMemorySize, smem_gemm);
    cudaFuncSetAttribute(k_dloo, cudaFuncAttributeMaxDynamicSharedMemorySize, smem_dloo);

    k_wsplit<<<64, 256>>>(W);
    k_gemm<<<M_TOT / 128, 512, smem_gemm>>>(xs, xq);
    k_proto<<<C_CLS, 128>>>();
    k_dloo<<<128, 512, smem_dloo>>>();
    k_final<<<1, 1>>>(out);
}